// round 12
// baseline (speedup 1.0000x reference)
#include <cuda_runtime.h>

// ============================================================================
// PGALoss — analytically reduced.
// gp(P,Q) for embedded PGA points = -1 + (q-p) in e01/e02/e03
//   => ||gp|| = sqrt(1+d^2), ||dual(P-Q)|| = d   (d = Euclidean NN distance)
//   loss_dir = clip((mean[sqrt(1+d^2)+d] - 1)/2, 0, 1)
//   out = 0.5*(loss_dir0 + loss_dir1)
// Heavy part: brute-force 1-NN, 2 dirs x 2 batches x 8192^2 pairs via packed
// fma.rn.f32x2; candidate tile stored as interleaved longlong2 so one LDS.128
// yields two f32x2 operands with no repack MOVs.
// ============================================================================

#define NPTS     8192
#define NB       2
#define NDIR     2
#define THREADS  128
#define QPT      8                    // queries per thread
#define QPB      (THREADS * QPT)      // 1024 queries per block
#define QCHUNKS  (NPTS / QPB)         // 8
#define TILE     512                  // candidates per smem tile
#define CCHUNKS  (NPTS / TILE)        // 16
#define NQ_TOTAL (NDIR * NB * NPTS)   // 32768

typedef unsigned long long ull_t;

#define FMA2(d, a, b, c) \
    asm("fma.rn.f32x2 %0, %1, %2, %3;" : "=l"(d) : "l"(a), "l"(b), "l"(c))

#define PACK2(d, lo, hi) \
    asm("mov.b64 %0, {%1, %2};" : "=l"(d) : "r"(__float_as_uint(lo)), "r"(__float_as_uint(hi)))

#define UNPACK2(lo, hi, v) do {                                     \
    unsigned int _ulo, _uhi;                                        \
    asm("mov.b64 {%0, %1}, %2;" : "=r"(_ulo), "=r"(_uhi) : "l"(v)); \
    lo = __uint_as_float(_ulo); hi = __uint_as_float(_uhi);         \
} while (0)

// Scratch: per-query min squared distance, monotonic uint bits (d2 >= 0).
__device__ unsigned int g_min[NQ_TOTAL];

__global__ void init_kernel() {
    // 32768 uints as 8192 uint4 stores: 8 blocks x 1024 threads.
    uint4* p = (uint4*)g_min;
    p[blockIdx.x * 1024 + threadIdx.x] =
        make_uint4(0x7F800000u, 0x7F800000u, 0x7F800000u, 0x7F800000u);  // +inf
}

__global__ __launch_bounds__(THREADS, 4)
void nn_kernel(const float* __restrict__ src, const float* __restrict__ tgt) {
    int bid = blockIdx.x;
    int cc  = bid & (CCHUNKS - 1);  bid >>= 4;   // log2(CCHUNKS)=4
    int qc  = bid & (QCHUNKS - 1);  bid >>= 3;   // log2(QCHUNKS)=3
    int b   = bid & 1;
    int dir = bid >> 1;

    const float* qry  = (dir == 0) ? src : tgt;
    const float* cand = (dir == 0) ? tgt : src;
    qry  += (size_t)b * NPTS * 3;
    cand += (size_t)b * NPTS * 3;

    // Candidate pair j: sA[j] = bits(x0,x1,y0,y1), sB[j] = bits(z0,z1,w0,w1)
    // where w = |p|^2. One LDS.128 -> two f32x2 operands, naturally reg-paired.
    __shared__ longlong2 sA[TILE / 2];
    __shared__ longlong2 sB[TILE / 2];

    const int tid = threadIdx.x;

    for (int p = tid; p < TILE / 2; p += THREADS) {
        int ci = cc * TILE + 2 * p;
        float x0 = cand[ci * 3 + 0], y0 = cand[ci * 3 + 1], z0 = cand[ci * 3 + 2];
        float x1 = cand[ci * 3 + 3], y1 = cand[ci * 3 + 4], z1 = cand[ci * 3 + 5];
        float w0 = fmaf(x0, x0, fmaf(y0, y0, z0 * z0));
        float w1 = fmaf(x1, x1, fmaf(y1, y1, z1 * z1));
        float* a  = (float*)&sA[p];
        float* bb = (float*)&sB[p];
        a[0] = x0; a[1] = x1; a[2] = y0; a[3] = y1;
        bb[0] = z0; bb[1] = z1; bb[2] = w0; bb[3] = w1;
    }
    __syncthreads();

    // Per-thread queries: packed broadcast constants (-2qx,-2qx) etc.
    ull_t qx2[QPT], qy2[QPT], qz2[QPT];
    float q2[QPT], mn[QPT];
#pragma unroll
    for (int k = 0; k < QPT; k++) {
        int qi = qc * QPB + k * THREADS + tid;
        float x = qry[qi * 3 + 0];
        float y = qry[qi * 3 + 1];
        float z = qry[qi * 3 + 2];
        float mx = -2.0f * x, my = -2.0f * y, mz = -2.0f * z;
        PACK2(qx2[k], mx, mx);
        PACK2(qy2[k], my, my);
        PACK2(qz2[k], mz, mz);
        q2[k] = fmaf(x, x, fmaf(y, y, z * z));
        mn[k] = 3.4e38f;
    }

    // Per iter (2 candidates x 8 queries): 2 LDS.128 + 24 FFMA2 + 16 FMNMX.
    // score(q,p) = |p|^2 - 2 q.p  (min over p; +|q|^2 deferred)
#pragma unroll 4
    for (int j = 0; j < TILE / 2; j++) {
        longlong2 A = sA[j];   // A.x = (x0,x1), A.y = (y0,y1)
        longlong2 B = sB[j];   // B.x = (z0,z1), B.y = (w0,w1)
#pragma unroll
        for (int k = 0; k < QPT; k++) {
            ull_t s;
            FMA2(s, qz2[k], B.x, B.y);
            FMA2(s, qy2[k], A.y, s);
            FMA2(s, qx2[k], A.x, s);
            float lo, hi;
            UNPACK2(lo, hi, s);
            mn[k] = fminf(mn[k], fminf(lo, hi));
        }
    }

#pragma unroll
    for (int k = 0; k < QPT; k++) {
        int qi = qc * QPB + k * THREADS + tid;
        float d2 = fmaxf(mn[k] + q2[k], 0.0f);   // clamp cancellation
        unsigned int* slot = &g_min[((size_t)(dir * NB + b)) * NPTS + qi];
        atomicMin(slot, __float_as_uint(d2));    // exact, order-independent
    }
}

__global__ void reduce_kernel(float* __restrict__ out) {
    __shared__ float s0[1024];
    __shared__ float s1[1024];
    const int tid = threadIdx.x;

    float a0 = 0.0f, a1 = 0.0f;
    for (int i = tid; i < NB * NPTS; i += 1024) {
        float d2 = __uint_as_float(g_min[i]);
        a0 += sqrtf(1.0f + d2) + sqrtf(d2);
        float e2 = __uint_as_float(g_min[NB * NPTS + i]);
        a1 += sqrtf(1.0f + e2) + sqrtf(e2);
    }
    s0[tid] = a0;
    s1[tid] = a1;
    __syncthreads();

    for (int off = 512; off > 0; off >>= 1) {
        if (tid < off) { s0[tid] += s0[tid + off]; s1[tid] += s1[tid + off]; }
        __syncthreads();
    }

    if (tid == 0) {
        const float inv = 1.0f / (float)(NB * NPTS);
        float l0 = (s0[0] * inv - 1.0f) * 0.5f;
        float l1 = (s1[0] * inv - 1.0f) * 0.5f;
        l0 = fminf(fmaxf(l0, 0.0f), 1.0f);
        l1 = fminf(fmaxf(l1, 0.0f), 1.0f);
        out[0] = 0.5f * (l0 + l1);
    }
}

extern "C" void kernel_launch(void* const* d_in, const int* in_sizes, int n_in,
                              void* d_out, int out_size) {
    const float* src = (const float*)d_in[0];   // source_points (2,8192,3) f32
    const float* tgt = (const float*)d_in[1];   // target_points (2,8192,3) f32
    (void)in_sizes; (void)n_in; (void)out_size;

    init_kernel<<<NQ_TOTAL / 4096, 1024>>>();
    nn_kernel<<<NDIR * NB * QCHUNKS * CCHUNKS, THREADS>>>(src, tgt);
    reduce_kernel<<<1, 1024>>>((float*)d_out);
}

// round 16
// speedup vs baseline: 1.0467x; 1.0467x over previous
#include <cuda_runtime.h>

// ============================================================================
// PGALoss — analytically reduced + SYMMETRY: dist matrix between src and tgt
// is shared by both NN directions (row mins vs col mins). Each of the
// 2 x 8192 x 8192 scores is computed ONCE (was twice) and feeds both sides.
//   loss_dir = clip((mean[sqrt(1+d^2)+d] - 1)/2, 0, 1); out = avg of 2 dirs.
// Scores via packed fma.rn.f32x2 with q^2 folded into the base so row AND col
// accumulations see true |q-p|^2.
// ============================================================================

#define NPTS     8192
#define NB       2
#define THREADS  128
#define QPT      8                    // src queries per thread
#define QPB      (THREADS * QPT)      // 1024 queries per block
#define QCHUNKS  (NPTS / QPB)         // 8
#define TILE     256                  // tgt candidates per smem tile
#define CCHUNKS  (NPTS / TILE)        // 32
#define NQ_TOTAL (2 * NB * NPTS)      // side0: src mins, side1: tgt mins

typedef unsigned long long ull_t;

#define FMA2(d, a, b, c) \
    asm("fma.rn.f32x2 %0, %1, %2, %3;" : "=l"(d) : "l"(a), "l"(b), "l"(c))

#define ADD2(d, a, b) \
    asm("add.rn.f32x2 %0, %1, %2;" : "=l"(d) : "l"(a), "l"(b))

#define PACK2(d, lo, hi) \
    asm("mov.b64 %0, {%1, %2};" : "=l"(d) : "r"(__float_as_uint(lo)), "r"(__float_as_uint(hi)))

#define UNPACK2(lo, hi, v) do {                                     \
    unsigned int _ulo, _uhi;                                        \
    asm("mov.b64 {%0, %1}, %2;" : "=r"(_ulo), "=r"(_uhi) : "l"(v)); \
    lo = __uint_as_float(_ulo); hi = __uint_as_float(_uhi);         \
} while (0)

// Monotone float->u32 map (unsigned order == float order), and inverse.
__device__ __forceinline__ unsigned fkey(float f) {
    unsigned b = __float_as_uint(f);
    return b ^ (unsigned)(((int)b >> 31) | 0x80000000);
}
__device__ __forceinline__ float funkey(unsigned k) {
    unsigned b = (k & 0x80000000u) ? (k ^ 0x80000000u) : ~k;
    return __uint_as_float(b);
}

// Scratch: per-point min squared distance, raw nonneg-float bits.
__device__ unsigned int g_min[NQ_TOTAL];

__global__ void init_kernel() {
    uint4* p = (uint4*)g_min;
    p[blockIdx.x * 1024 + threadIdx.x] =
        make_uint4(0x7F800000u, 0x7F800000u, 0x7F800000u, 0x7F800000u);  // +inf
}

__global__ __launch_bounds__(THREADS, 4)
void nn_kernel(const float* __restrict__ src, const float* __restrict__ tgt) {
    int bid = blockIdx.x;
    int cc  = bid & (CCHUNKS - 1);  bid >>= 5;   // log2(32)=5
    int qc  = bid & (QCHUNKS - 1);  bid >>= 3;   // log2(8)=3
    int b   = bid;                                // 0..1

    const float* qry  = src + (size_t)b * NPTS * 3;   // rows  (side 0)
    const float* cand = tgt + (size_t)b * NPTS * 3;   // cols  (side 1)

    // Candidate pair j: sA[j]=(x0,x1,y0,y1), sB[j]=(z0,z1,w0,w1), w=|p|^2.
    __shared__ longlong2 sA[TILE / 2];
    __shared__ longlong2 sB[TILE / 2];
    __shared__ unsigned  scol[TILE];   // per-candidate min key (mapped u32)

    const int tid  = threadIdx.x;
    const int lane = tid & 31;

    {   // one candidate pair per thread (TILE/2 == THREADS)
        int ci = cc * TILE + 2 * tid;
        float x0 = cand[ci * 3 + 0], y0 = cand[ci * 3 + 1], z0 = cand[ci * 3 + 2];
        float x1 = cand[ci * 3 + 3], y1 = cand[ci * 3 + 4], z1 = cand[ci * 3 + 5];
        float w0 = fmaf(x0, x0, fmaf(y0, y0, z0 * z0));
        float w1 = fmaf(x1, x1, fmaf(y1, y1, z1 * z1));
        float* a  = (float*)&sA[tid];
        float* bb = (float*)&sB[tid];
        a[0] = x0; a[1] = x1; a[2] = y0; a[3] = y1;
        bb[0] = z0; bb[1] = z1; bb[2] = w0; bb[3] = w1;
        scol[2 * tid]     = 0xFFFFFFFFu;
        scol[2 * tid + 1] = 0xFFFFFFFFu;
    }
    __syncthreads();

    // Per-thread queries: packed (-2q) components and packed |q|^2.
    ull_t qx2[QPT], qy2[QPT], qz2[QPT], q2P[QPT];
    float mn[QPT];
#pragma unroll
    for (int k = 0; k < QPT; k++) {
        int qi = qc * QPB + k * THREADS + tid;
        float x = qry[qi * 3 + 0];
        float y = qry[qi * 3 + 1];
        float z = qry[qi * 3 + 2];
        float mx = -2.0f * x, my = -2.0f * y, mz = -2.0f * z;
        float q2 = fmaf(x, x, fmaf(y, y, z * z));
        PACK2(qx2[k], mx, mx);
        PACK2(qy2[k], my, my);
        PACK2(qz2[k], mz, mz);
        PACK2(q2P[k], q2, q2);
        mn[k] = 3.4e38f;
    }

    // Main loop: score s = |q|^2 + |p|^2 - 2 q.p  (true squared distance),
    // 2 candidates per packed chain; feeds BOTH row mins and col mins.
#pragma unroll 2
    for (int j = 0; j < TILE / 2; j++) {
        longlong2 A = sA[j];   // (x0,x1), (y0,y1)
        longlong2 B = sB[j];   // (z0,z1), (w0,w1)
        float c0 = 3.4e38f, c1 = 3.4e38f;
#pragma unroll
        for (int k = 0; k < QPT; k++) {
            ull_t base, s;
            ADD2(base, B.y, q2P[k]);          // w + |q|^2
            FMA2(s, qz2[k], B.x, base);
            FMA2(s, qy2[k], A.y, s);
            FMA2(s, qx2[k], A.x, s);
            float lo, hi;
            UNPACK2(lo, hi, s);
            mn[k] = fminf(mn[k], fminf(lo, hi));   // row mins (src side)
            c0 = fminf(c0, lo);                    // col mins (tgt side)
            c1 = fminf(c1, hi);
        }
        // warp-wide col min, then 4 warps combine in smem
        unsigned k0 = __reduce_min_sync(0xFFFFFFFFu, fkey(c0));
        unsigned k1 = __reduce_min_sync(0xFFFFFFFFu, fkey(c1));
        if (lane == 0) {
            atomicMin(&scol[2 * j],     k0);
            atomicMin(&scol[2 * j + 1], k1);
        }
    }

    // Row epilogue: push src-side mins.
#pragma unroll
    for (int k = 0; k < QPT; k++) {
        int qi = qc * QPB + k * THREADS + tid;
        float d2 = fmaxf(mn[k], 0.0f);   // clamp rounding
        atomicMin(&g_min[(size_t)b * NPTS + qi], __float_as_uint(d2));
    }

    // Col epilogue: push tgt-side mins.
    __syncthreads();
    for (int c = tid; c < TILE; c += THREADS) {
        float d2 = fmaxf(funkey(scol[c]), 0.0f);
        atomicMin(&g_min[(size_t)(NB + b) * NPTS + cc * TILE + c],
                  __float_as_uint(d2));
    }
}

__global__ void reduce_kernel(float* __restrict__ out) {
    __shared__ float s0[1024];
    __shared__ float s1[1024];
    const int tid = threadIdx.x;

    float a0 = 0.0f, a1 = 0.0f;
    for (int i = tid; i < NB * NPTS; i += 1024) {
        float d2 = __uint_as_float(g_min[i]);                 // src side
        a0 += sqrtf(1.0f + d2) + sqrtf(d2);
        float e2 = __uint_as_float(g_min[NB * NPTS + i]);     // tgt side
        a1 += sqrtf(1.0f + e2) + sqrtf(e2);
    }
    s0[tid] = a0;
    s1[tid] = a1;
    __syncthreads();

    for (int off = 512; off > 0; off >>= 1) {
        if (tid < off) { s0[tid] += s0[tid + off]; s1[tid] += s1[tid + off]; }
        __syncthreads();
    }

    if (tid == 0) {
        const float inv = 1.0f / (float)(NB * NPTS);
        float l0 = (s0[0] * inv - 1.0f) * 0.5f;
        float l1 = (s1[0] * inv - 1.0f) * 0.5f;
        l0 = fminf(fmaxf(l0, 0.0f), 1.0f);
        l1 = fminf(fmaxf(l1, 0.0f), 1.0f);
        out[0] = 0.5f * (l0 + l1);
    }
}

extern "C" void kernel_launch(void* const* d_in, const int* in_sizes, int n_in,
                              void* d_out, int out_size) {
    const float* src = (const float*)d_in[0];   // source_points (2,8192,3) f32
    const float* tgt = (const float*)d_in[1];   // target_points (2,8192,3) f32
    (void)in_sizes; (void)n_in; (void)out_size;

    init_kernel<<<NQ_TOTAL / 4096, 1024>>>();
    nn_kernel<<<NB * QCHUNKS * CCHUNKS, THREADS>>>(src, tgt);
    reduce_kernel<<<1, 1024>>>((float*)d_out);
}